// round 1
// baseline (speedup 1.0000x reference)
#include <cuda_runtime.h>
#include <cstdint>

#define DIM 1024
#define NHEADS 16
#define HD 64
#define BATCH 4
#define SEQ 2048
#define M_ROWS (BATCH * SEQ)   // 8192

// ---------------- scratch (no allocs allowed) ----------------
__device__ float g_xq[M_ROWS * DIM];
__device__ float g_xk[M_ROWS * DIM];
__device__ float g_xv[M_ROWS * DIM];
__device__ float g_ao[M_ROWS * DIM];

// ---------------- SGEMM: C[M,N] = A[M,K] @ B[K,N], row-major ----------------
#define BM 128
#define BN 128
#define BK 8

__global__ __launch_bounds__(256) void sgemm_kernel(
    const float* __restrict__ A, const float* __restrict__ B,
    float* __restrict__ C, int M, int N, int K)
{
    __shared__ float As[BK][BM + 4];
    __shared__ float Bs[BK][BN];

    const int tid = threadIdx.x;
    const int tm = tid >> 4;        // 0..15
    const int tn = tid & 15;        // 0..15
    const int bm = blockIdx.y * BM;
    const int bn = blockIdx.x * BN;

    const int ar  = tid >> 1;        // 0..127  A row in tile
    const int ak  = (tid & 1) * 4;   // 0 or 4  A k-offset
    const int bk  = tid >> 5;        // 0..7    B k row
    const int bn4 = (tid & 31) * 4;  // B col offset

    const float* Ab = A + (size_t)(bm + ar) * K + ak;
    const float* Bb = B + (size_t)bk * N + bn + bn4;

    float acc[8][8];
#pragma unroll
    for (int i = 0; i < 8; i++)
#pragma unroll
        for (int j = 0; j < 8; j++) acc[i][j] = 0.f;

    for (int k0 = 0; k0 < K; k0 += BK) {
        float4 av = *reinterpret_cast<const float4*>(Ab + k0);
        float4 bv = *reinterpret_cast<const float4*>(Bb + (size_t)k0 * N);
        As[ak + 0][ar] = av.x;
        As[ak + 1][ar] = av.y;
        As[ak + 2][ar] = av.z;
        As[ak + 3][ar] = av.w;
        *reinterpret_cast<float4*>(&Bs[bk][bn4]) = bv;
        __syncthreads();

#pragma unroll
        for (int k = 0; k < BK; k++) {
            float a[8], b[8];
#pragma unroll
            for (int i = 0; i < 8; i++) a[i] = As[k][tm * 8 + i];
#pragma unroll
            for (int j = 0; j < 8; j++) b[j] = Bs[k][tn * 8 + j];
#pragma unroll
            for (int i = 0; i < 8; i++)
#pragma unroll
                for (int j = 0; j < 8; j++)
                    acc[i][j] += a[i] * b[j];
        }
        __syncthreads();
    }

#pragma unroll
    for (int i = 0; i < 8; i++) {
        float* Crow = C + (size_t)(bm + tm * 8 + i) * N + bn + tn * 8;
        float4 v0 = make_float4(acc[i][0], acc[i][1], acc[i][2], acc[i][3]);
        float4 v1 = make_float4(acc[i][4], acc[i][5], acc[i][6], acc[i][7]);
        reinterpret_cast<float4*>(Crow)[0] = v0;
        reinterpret_cast<float4*>(Crow)[1] = v1;
    }
}

// ---------------- causal flash attention, fp32 ----------------
// xq/xk/xv layout: [B, S, DIM] where head h occupies cols [h*64, h*64+64)
#define QT 64
#define KT 64
#define ASTR 65   // smem row stride (odd -> <=2-way conflicts on column reads)

__global__ __launch_bounds__(256) void attn_kernel(
    const float* __restrict__ XQ, const float* __restrict__ XK,
    const float* __restrict__ XV, float* __restrict__ O)
{
    extern __shared__ float sm[];
    float* Qs = sm;                  // [64][65]
    float* Ks = sm + QT * ASTR;      // [64][65]
    float* Vs = sm + 2 * QT * ASTR;  // [64][65]
    float* Ss = sm + 3 * QT * ASTR;  // [64][65]

    const int tid = threadIdx.x;
    const int bh = blockIdx.y;        // b*NHEADS + h
    const int b = bh >> 4;
    const int h = bh & 15;
    const int q0 = blockIdx.x * QT;

    const int tm = tid >> 4, tn = tid & 15;
    const int r0 = tm * 4, c0 = tn * 4;

    const int lr = tid >> 2;          // 0..63 (tile row for loads)
    const int lc = (tid & 3) * 16;    // 0/16/32/48

    // load Q tile (pre-scaled by 1/sqrt(64))
    {
        const float* qb = XQ + ((size_t)(b * SEQ + q0 + lr) * DIM) + h * HD + lc;
        const float4* src = reinterpret_cast<const float4*>(qb);
#pragma unroll
        for (int u = 0; u < 4; u++) {
            float4 v = src[u];
            float* d = &Qs[lr * ASTR + lc + u * 4];
            d[0] = v.x * 0.125f; d[1] = v.y * 0.125f;
            d[2] = v.z * 0.125f; d[3] = v.w * 0.125f;
        }
    }

    float m_s[4], l_s[4], o[4][4];
#pragma unroll
    for (int i = 0; i < 4; i++) {
        m_s[i] = -1e30f;
        l_s[i] = 0.f;
#pragma unroll
        for (int j = 0; j < 4; j++) o[i][j] = 0.f;
    }

    const float* kbase = XK + ((size_t)(b * SEQ) * DIM) + h * HD;
    const float* vbase = XV + ((size_t)(b * SEQ) * DIM) + h * HD;

    for (int jt = 0; jt <= (int)blockIdx.x; jt++) {
        const int k0g = jt * KT;
        __syncthreads();   // prev iteration's readers of Ks/Vs/Ss done (also covers Qs writes on iter 0)

        // load K & V tiles
        {
            const float4* ks = reinterpret_cast<const float4*>(
                kbase + (size_t)(k0g + lr) * DIM + lc);
            const float4* vs = reinterpret_cast<const float4*>(
                vbase + (size_t)(k0g + lr) * DIM + lc);
#pragma unroll
            for (int u = 0; u < 4; u++) {
                float4 kv = ks[u];
                float4 vv = vs[u];
                float* kd = &Ks[lr * ASTR + lc + u * 4];
                float* vd = &Vs[lr * ASTR + lc + u * 4];
                kd[0] = kv.x; kd[1] = kv.y; kd[2] = kv.z; kd[3] = kv.w;
                vd[0] = vv.x; vd[1] = vv.y; vd[2] = vv.z; vd[3] = vv.w;
            }
        }
        __syncthreads();

        // S = Q @ K^T (4x4 micro-tile)
        float s[4][4];
#pragma unroll
        for (int i = 0; i < 4; i++)
#pragma unroll
            for (int j = 0; j < 4; j++) s[i][j] = 0.f;

#pragma unroll 8
        for (int k = 0; k < HD; k++) {
            float qa[4], kb[4];
#pragma unroll
            for (int i = 0; i < 4; i++) qa[i] = Qs[(r0 + i) * ASTR + k];
#pragma unroll
            for (int j = 0; j < 4; j++) kb[j] = Ks[(c0 + j) * ASTR + k];
#pragma unroll
            for (int i = 0; i < 4; i++)
#pragma unroll
                for (int j = 0; j < 4; j++)
                    s[i][j] += qa[i] * kb[j];
        }

        if (jt == (int)blockIdx.x) {   // diagonal tile: causal mask (key > query)
#pragma unroll
            for (int i = 0; i < 4; i++)
#pragma unroll
                for (int j = 0; j < 4; j++)
                    if (k0g + c0 + j > q0 + r0 + i) s[i][j] = -1e30f;
        }

        // online softmax: rows owned by 16 lanes sharing tm (half-warp reductions)
#pragma unroll
        for (int i = 0; i < 4; i++) {
            float rm = fmaxf(fmaxf(s[i][0], s[i][1]), fmaxf(s[i][2], s[i][3]));
#pragma unroll
            for (int d = 8; d >= 1; d >>= 1)
                rm = fmaxf(rm, __shfl_xor_sync(0xffffffffu, rm, d));
            float mn = fmaxf(m_s[i], rm);
            float alpha = __expf(m_s[i] - mn);
            float rs = 0.f;
#pragma unroll
            for (int j = 0; j < 4; j++) {
                float p = __expf(s[i][j] - mn);
                s[i][j] = p;
                rs += p;
            }
#pragma unroll
            for (int d = 8; d >= 1; d >>= 1)
                rs += __shfl_xor_sync(0xffffffffu, rs, d);
            l_s[i] = l_s[i] * alpha + rs;
            m_s[i] = mn;
#pragma unroll
            for (int j = 0; j < 4; j++) o[i][j] *= alpha;
        }

        // publish P
#pragma unroll
        for (int i = 0; i < 4; i++)
#pragma unroll
            for (int j = 0; j < 4; j++)
                Ss[(r0 + i) * ASTR + c0 + j] = s[i][j];
        __syncthreads();

        // O += P @ V (4x4 micro-tile)
#pragma unroll 4
        for (int k = 0; k < KT; k++) {
            float pv[4], vv[4];
#pragma unroll
            for (int i = 0; i < 4; i++) pv[i] = Ss[(r0 + i) * ASTR + k];
#pragma unroll
            for (int j = 0; j < 4; j++) vv[j] = Vs[k * ASTR + c0 + j];
#pragma unroll
            for (int i = 0; i < 4; i++)
#pragma unroll
                for (int j = 0; j < 4; j++)
                    o[i][j] += pv[i] * vv[j];
        }
    }

    // normalize + write (layout [B, S, DIM], head h at col h*64)
    float* obase = O + ((size_t)(b * SEQ + q0) * DIM) + h * HD;
#pragma unroll
    for (int i = 0; i < 4; i++) {
        float inv = 1.0f / l_s[i];
        float4 v = make_float4(o[i][0] * inv, o[i][1] * inv,
                               o[i][2] * inv, o[i][3] * inv);
        *reinterpret_cast<float4*>(obase + (size_t)(r0 + i) * DIM + c0) = v;
    }
}

// ---------------- launch ----------------
static const int ATTN_SMEM = 4 * QT * ASTR * (int)sizeof(float);  // 66560 B

extern "C" void kernel_launch(void* const* d_in, const int* in_sizes, int n_in,
                              void* d_out, int out_size)
{
    const float* q  = (const float*)d_in[0];
    const float* k  = (const float*)d_in[1];
    const float* v  = (const float*)d_in[2];
    const float* wq = (const float*)d_in[3];
    const float* wk = (const float*)d_in[4];
    const float* wv = (const float*)d_in[5];
    const float* wo = (const float*)d_in[6];
    float* out = (float*)d_out;

    float *xq, *xk, *xv, *ao;
    cudaGetSymbolAddress((void**)&xq, g_xq);
    cudaGetSymbolAddress((void**)&xk, g_xk);
    cudaGetSymbolAddress((void**)&xv, g_xv);
    cudaGetSymbolAddress((void**)&ao, g_ao);

    cudaFuncSetAttribute(attn_kernel,
                         cudaFuncAttributeMaxDynamicSharedMemorySize, ATTN_SMEM);

    dim3 gg(DIM / BN, M_ROWS / BM);   // (8, 64)
    sgemm_kernel<<<gg, 256>>>(q, wq, xq, M_ROWS, DIM, DIM);
    sgemm_kernel<<<gg, 256>>>(k, wk, xk, M_ROWS, DIM, DIM);
    sgemm_kernel<<<gg, 256>>>(v, wv, xv, M_ROWS, DIM, DIM);

    dim3 ga(SEQ / QT, BATCH * NHEADS);  // (32, 64)
    attn_kernel<<<ga, 256, ATTN_SMEM>>>(xq, xk, xv, ao);

    sgemm_kernel<<<gg, 256>>>(ao, wo, out, M_ROWS, DIM, DIM);
}

// round 6
// speedup vs baseline: 1.5716x; 1.5716x over previous
#include <cuda_runtime.h>
#include <cuda_bf16.h>
#include <cstdint>

#define DIM 1024
#define NHEADS 16
#define HD 64
#define BATCH 4
#define SEQ 2048
#define M_ROWS (BATCH * SEQ)   // 8192

// ---------------- scratch (no allocs allowed) ----------------
__device__ float g_xq[M_ROWS * DIM];
__device__ float g_xk[M_ROWS * DIM];
__device__ float g_xv[M_ROWS * DIM];
__device__ float g_ao[M_ROWS * DIM];
__device__ __nv_bfloat16 g_ahi[M_ROWS * DIM];
__device__ __nv_bfloat16 g_alo[M_ROWS * DIM];
__device__ __nv_bfloat16 g_wthi[4 * DIM * DIM];   // W^T hi, [n][k]
__device__ __nv_bfloat16 g_wtlo[4 * DIM * DIM];   // W^T lo

// ================= helpers =================
__device__ __forceinline__ uint32_t smem_to_u32(const void* p) {
    uint32_t a;
    asm("{ .reg .u64 t; cvta.to.shared.u64 t, %1; cvt.u32.u64 %0, t; }"
        : "=r"(a) : "l"(p));
    return a;
}

#define CP_ASYNC16(saddr, gptr) \
    asm volatile("cp.async.cg.shared.global [%0], [%1], 16;" \
                 :: "r"(saddr), "l"(gptr) : "memory")
#define CP_COMMIT() asm volatile("cp.async.commit_group;" ::: "memory")
#define CP_WAIT1() asm volatile("cp.async.wait_group 1;" ::: "memory")
#define CP_WAIT0() asm volatile("cp.async.wait_group 0;" ::: "memory")

#define MMA16816(c, a, b) \
    asm volatile("mma.sync.aligned.m16n8k16.row.col.f32.bf16.bf16.f32 " \
        "{%0,%1,%2,%3}, {%4,%5,%6,%7}, {%8,%9}, {%0,%1,%2,%3};" \
        : "+f"((c)[0]), "+f"((c)[1]), "+f"((c)[2]), "+f"((c)[3]) \
        : "r"((a)[0]), "r"((a)[1]), "r"((a)[2]), "r"((a)[3]), \
          "r"((b)[0]), "r"((b)[1]))

// ================= prep kernels =================
// split fp32 -> hi/lo bf16 (same layout), 4 floats per thread
__global__ __launch_bounds__(256) void split_a(const float4* __restrict__ in,
                                               uint2* __restrict__ oh,
                                               uint2* __restrict__ ol) {
    int idx = blockIdx.x * 256 + threadIdx.x;   // over M_ROWS*DIM/4
    float4 v = in[idx];
    __nv_bfloat162 h01, h23, l01, l23;
    h01.x = __float2bfloat16(v.x); h01.y = __float2bfloat16(v.y);
    h23.x = __float2bfloat16(v.z); h23.y = __float2bfloat16(v.w);
    l01.x = __float2bfloat16(v.x - __bfloat162float(h01.x));
    l01.y = __float2bfloat16(v.y - __bfloat162float(h01.y));
    l23.x = __float2bfloat16(v.z - __bfloat162float(h23.x));
    l23.y = __float2bfloat16(v.w - __bfloat162float(h23.y));
    uint2 rh, rl;
    rh.x = *reinterpret_cast<uint32_t*>(&h01); rh.y = *reinterpret_cast<uint32_t*>(&h23);
    rl.x = *reinterpret_cast<uint32_t*>(&l01); rl.y = *reinterpret_cast<uint32_t*>(&l23);
    oh[idx] = rh; ol[idx] = rl;
}

// transpose + split weights: Th/Tl[n][k] = hi/lo(W[k][n])
__global__ void wt_split(const float* __restrict__ W,
                         __nv_bfloat16* __restrict__ Th,
                         __nv_bfloat16* __restrict__ Tl) {
    __shared__ float t[32][33];
    int n0 = blockIdx.x * 32, k0 = blockIdx.y * 32;
    int tx = threadIdx.x, ty = threadIdx.y;   // (32,8)
#pragma unroll
    for (int i = ty; i < 32; i += 8)
        t[i][tx] = W[(size_t)(k0 + i) * DIM + n0 + tx];
    __syncthreads();
#pragma unroll
    for (int i = ty; i < 32; i += 8) {
        float x = t[tx][i];   // W[k0+tx][n0+i]
        __nv_bfloat16 h = __float2bfloat16(x);
        __nv_bfloat16 l = __float2bfloat16(x - __bfloat162float(h));
        size_t o = (size_t)(n0 + i) * DIM + k0 + tx;
        Th[o] = h; Tl[o] = l;
    }
}

// ================= bf16x3 mma.sync GEMM =================
// C[8192,1024] = A @ B.  A split hi/lo [M][K] bf16; B given as B^T split hi/lo [N][K] bf16.
// CTA 128x128, K-chunk 64, cp.async double buffer, warp tile 64x32, mma m16n8k16.
#define AROWB 144                 // smem bytes per 64-elem bf16 row (16B pad)
#define TILEB (128 * AROWB)       // 18432
#define BUFB (4 * TILEB)          // 73728: Ahi|Alo|Bhi|Blo
#define GSMEM (2 * BUFB)          // 147456

__global__ __launch_bounds__(256, 1) void gemm_mma(
    const __nv_bfloat16* __restrict__ Ahi, const __nv_bfloat16* __restrict__ Alo,
    const __nv_bfloat16* __restrict__ Bhi, const __nv_bfloat16* __restrict__ Blo,
    float* __restrict__ C)
{
    extern __shared__ char sm[];
    const uint32_t sb = smem_to_u32(sm);
    const int tid = threadIdx.x;
    const int wid = tid >> 5, lane = tid & 31;
    const int wm = wid >> 2, wn = wid & 3;       // 2x4 warp grid
    const int g = lane >> 2, t = lane & 3;
    const int m0 = blockIdx.y * 128, n0 = blockIdx.x * 128;

    float acc[4][4][4];
#pragma unroll
    for (int mi = 0; mi < 4; mi++)
#pragma unroll
        for (int ni = 0; ni < 4; ni++)
#pragma unroll
            for (int j = 0; j < 4; j++) acc[mi][ni][j] = 0.f;

    // per-thread load slots: flat = u*256+tid -> (row, seg) of a 128x(8x16B) tile
    uint32_t soff[4]; int arow[4], aseg[4];
#pragma unroll
    for (int u = 0; u < 4; u++) {
        int flat = u * 256 + tid;
        arow[u] = flat >> 3;
        aseg[u] = flat & 7;
        soff[u] = (uint32_t)(arow[u] * AROWB + aseg[u] * 16);
    }

    auto issue_chunk = [&](int c, int buf) {
        const int k0 = c * 64;
        const uint32_t bb = sb + buf * BUFB;
#pragma unroll
        for (int u = 0; u < 4; u++) {
            const size_t ga = (size_t)(m0 + arow[u]) * DIM + k0 + aseg[u] * 8;
            const size_t gb = (size_t)(n0 + arow[u]) * DIM + k0 + aseg[u] * 8;
            CP_ASYNC16(bb + 0 * TILEB + soff[u], Ahi + ga);
            CP_ASYNC16(bb + 1 * TILEB + soff[u], Alo + ga);
            CP_ASYNC16(bb + 2 * TILEB + soff[u], Bhi + gb);
            CP_ASYNC16(bb + 3 * TILEB + soff[u], Blo + gb);
        }
    };

    issue_chunk(0, 0);
    CP_COMMIT();

    for (int c = 0; c < DIM / 64; c++) {
        if (c < DIM / 64 - 1) {
            issue_chunk(c + 1, (c + 1) & 1);
            CP_COMMIT();
            CP_WAIT1();
        } else {
            CP_WAIT0();
        }
        __syncthreads();

        const char* bbp = sm + (c & 1) * BUFB;
#pragma unroll
        for (int ks = 0; ks < 4; ks++) {
            const int kb = ks * 32 + t * 4;   // byte offset of k = ks*16 + 2t
            uint32_t bh[4][2], bl[4][2];
#pragma unroll
            for (int ni = 0; ni < 4; ni++) {
                const uint32_t noff = (uint32_t)((wn * 32 + ni * 8 + g) * AROWB);
                bh[ni][0] = *(const uint32_t*)(bbp + 2 * TILEB + noff + kb);
                bh[ni][1] = *(const uint32_t*)(bbp + 2 * TILEB + noff + kb + 16);
                bl[ni][0] = *(const uint32_t*)(bbp + 3 * TILEB + noff + kb);
                bl[ni][1] = *(const uint32_t*)(bbp + 3 * TILEB + noff + kb + 16);
            }
#pragma unroll
            for (int mi = 0; mi < 4; mi++) {
                const uint32_t r0off = (uint32_t)((wm * 64 + mi * 16 + g) * AROWB);
                const uint32_t r1off = r0off + 8 * AROWB;
                uint32_t ah[4], al[4];
                ah[0] = *(const uint32_t*)(bbp + r0off + kb);
                ah[1] = *(const uint32_t*)(bbp + r1off + kb);
                ah[2] = *(const uint32_t*)(bbp + r0off + kb + 16);
                ah[3] = *(const uint32_t*)(bbp + r1off + kb + 16);
                al[0] = *(const uint32_t*)(bbp + TILEB + r0off + kb);
                al[1] = *(const uint32_t*)(bbp + TILEB + r1off + kb);
                al[2] = *(const uint32_t*)(bbp + TILEB + r0off + kb + 16);
                al[3] = *(const uint32_t*)(bbp + TILEB + r1off + kb + 16);
#pragma unroll
                for (int ni = 0; ni < 4; ni++) {
                    MMA16816(acc[mi][ni], ah, bh[ni]);
                    MMA16816(acc[mi][ni], ah, bl[ni]);
                    MMA16816(acc[mi][ni], al, bh[ni]);
                }
            }
        }
        __syncthreads();
    }

    // epilogue: fp32 accumulators straight to gmem
#pragma unroll
    for (int mi = 0; mi < 4; mi++) {
        const int r = m0 + wm * 64 + mi * 16 + g;
#pragma unroll
        for (int ni = 0; ni < 4; ni++) {
            const int cc = n0 + wn * 32 + ni * 8 + 2 * t;
            *reinterpret_cast<float2*>(C + (size_t)r * DIM + cc) =
                make_float2(acc[mi][ni][0], acc[mi][ni][1]);
            *reinterpret_cast<float2*>(C + (size_t)(r + 8) * DIM + cc) =
                make_float2(acc[mi][ni][2], acc[mi][ni][3]);
        }
    }
}

// ---------------- causal flash attention, fp32 (unchanged) ----------------
#define QT 64
#define KT 64
#define ASTR 65

__global__ __launch_bounds__(256) void attn_kernel(
    const float* __restrict__ XQ, const float* __restrict__ XK,
    const float* __restrict__ XV, float* __restrict__ O)
{
    extern __shared__ float smf[];
    float* Qs = smf;
    float* Ks = smf + QT * ASTR;
    float* Vs = smf + 2 * QT * ASTR;
    float* Ss = smf + 3 * QT * ASTR;

    const int tid = threadIdx.x;
    const int bh = blockIdx.y;
    const int b = bh >> 4;
    const int h = bh & 15;
    const int q0 = blockIdx.x * QT;

    const int tm = tid >> 4, tn = tid & 15;
    const int r0 = tm * 4, c0 = tn * 4;
    const int lr = tid >> 2;
    const int lc = (tid & 3) * 16;

    {
        const float* qb = XQ + ((size_t)(b * SEQ + q0 + lr) * DIM) + h * HD + lc;
        const float4* src = reinterpret_cast<const float4*>(qb);
#pragma unroll
        for (int u = 0; u < 4; u++) {
            float4 v = src[u];
            float* d = &Qs[lr * ASTR + lc + u * 4];
            d[0] = v.x * 0.125f; d[1] = v.y * 0.125f;
            d[2] = v.z * 0.125f; d[3] = v.w * 0.125f;
        }
    }

    float m_s[4], l_s[4], o[4][4];
#pragma unroll
    for (int i = 0; i < 4; i++) {
        m_s[i] = -1e30f; l_s[i] = 0.f;
#pragma unroll
        for (int j = 0; j < 4; j++) o[i][j] = 0.f;
    }

    const float* kbase = XK + ((size_t)(b * SEQ) * DIM) + h * HD;
    const float* vbase = XV + ((size_t)(b * SEQ) * DIM) + h * HD;

    for (int jt = 0; jt <= (int)blockIdx.x; jt++) {
        const int k0g = jt * KT;
        __syncthreads();
        {
            const float4* ks = reinterpret_cast<const float4*>(kbase + (size_t)(k0g + lr) * DIM + lc);
            const float4* vs = reinterpret_cast<const float4*>(vbase + (size_t)(k0g + lr) * DIM + lc);
#pragma unroll
            for (int u = 0; u < 4; u++) {
                float4 kv = ks[u]; float4 vv = vs[u];
                float* kd = &Ks[lr * ASTR + lc + u * 4];
                float* vd = &Vs[lr * ASTR + lc + u * 4];
                kd[0] = kv.x; kd[1] = kv.y; kd[2] = kv.z; kd[3] = kv.w;
                vd[0] = vv.x; vd[1] = vv.y; vd[2] = vv.z; vd[3] = vv.w;
            }
        }
        __syncthreads();

        float s[4][4];
#pragma unroll
        for (int i = 0; i < 4; i++)
#pragma unroll
            for (int j = 0; j < 4; j++) s[i][j] = 0.f;

#pragma unroll 8
        for (int k = 0; k < HD; k++) {
            float qa[4], kb[4];
#pragma unroll
            for (int i = 0; i < 4; i++) qa[i] = Qs[(r0 + i) * ASTR + k];
#pragma unroll
            for (int j = 0; j < 4; j++) kb[j] = Ks[(c0 + j) * ASTR + k];
#pragma unroll
            for (int i = 0; i < 4; i++)
#pragma unroll
                for (int j = 0; j < 4; j++)
                    s[i][j] += qa[i] * kb[j];
        }

        if (jt == (int)blockIdx.x) {
#pragma unroll
            for (int i = 0; i < 4; i++)
#pragma unroll
                for (int j = 0; j < 4; j++)
                    if (k0g + c0 + j > q0 + r0 + i) s[i][j] = -1e30f;
        }

#pragma unroll
        for (int i = 0; i < 4; i++) {
            float rm = fmaxf(fmaxf(s[i][0], s[i][1]), fmaxf(s[i][2], s[i][3]));
#pragma unroll
            for (int d = 8; d >= 1; d >>= 1)
                rm = fmaxf(rm, __shfl_xor_sync(0xffffffffu, rm, d));
            float mn = fmaxf(m_s[i], rm);
            float alpha = __expf(m_s[i] - mn);
            float rs = 0.f;
#pragma unroll
            for (int j = 0; j < 4; j++) {
                float p = __expf(s[i][j] - mn);
                s[i][j] = p; rs += p;
            }
#pragma unroll
            for (int d = 8; d >= 1; d >>= 1)
                rs += __shfl_xor_sync(0xffffffffu, rs, d);
            l_s[i] = l_s[i] * alpha + rs;
            m_s[i] = mn;
#pragma unroll
            for (int j = 0; j < 4; j++) o[i][j] *= alpha;
        }

#pragma unroll
        for (int i = 0; i < 4; i++)
#pragma unroll
            for (int j = 0; j < 4; j++)
                Ss[(r0 + i) * ASTR + c0 + j] = s[i][j];
        __syncthreads();

#pragma unroll 4
        for (int k = 0; k < KT; k++) {
            float pv[4], vv[4];
#pragma unroll
            for (int i = 0; i < 4; i++) pv[i] = Ss[(r0 + i) * ASTR + k];
#pragma unroll
            for (int j = 0; j < 4; j++) vv[j] = Vs[k * ASTR + c0 + j];
#pragma unroll
            for (int i = 0; i < 4; i++)
#pragma unroll
                for (int j = 0; j < 4; j++)
                    o[i][j] += pv[i] * vv[j];
        }
    }

    float* obase = O + ((size_t)(b * SEQ + q0) * DIM) + h * HD;
#pragma unroll
    for (int i = 0; i < 4; i++) {
        float inv = 1.0f / l_s[i];
        float4 v = make_float4(o[i][0] * inv, o[i][1] * inv, o[i][2] * inv, o[i][3] * inv);
        *reinterpret_cast<float4*>(obase + (size_t)(r0 + i) * DIM + c0) = v;
    }
}

// ---------------- launch ----------------
static const int ATTN_SMEM = 4 * QT * ASTR * (int)sizeof(float);  // 66560 B

extern "C" void kernel_launch(void* const* d_in, const int* in_sizes, int n_in,
                              void* d_out, int out_size)
{
    const float* q  = (const float*)d_in[0];
    const float* k  = (const float*)d_in[1];
    const float* v  = (const float*)d_in[2];
    const float* wq = (const float*)d_in[3];
    const float* wk = (const float*)d_in[4];
    const float* wv = (const float*)d_in[5];
    const float* wo = (const float*)d_in[6];
    float* out = (float*)d_out;

    float *xq, *xk, *xv, *ao;
    __nv_bfloat16 *ahi, *alo, *wthi, *wtlo;
    cudaGetSymbolAddress((void**)&xq, g_xq);
    cudaGetSymbolAddress((void**)&xk, g_xk);
    cudaGetSymbolAddress((void**)&xv, g_xv);
    cudaGetSymbolAddress((void**)&ao, g_ao);
    cudaGetSymbolAddress((void**)&ahi, g_ahi);
    cudaGetSymbolAddress((void**)&alo, g_alo);
    cudaGetSymbolAddress((void**)&wthi, g_wthi);
    cudaGetSymbolAddress((void**)&wtlo, g_wtlo);

    cudaFuncSetAttribute(attn_kernel, cudaFuncAttributeMaxDynamicSharedMemorySize, ATTN_SMEM);
    cudaFuncSetAttribute(gemm_mma, cudaFuncAttributeMaxDynamicSharedMemorySize, GSMEM);

    // weight transpose+split (4x)
    const float* ws[4] = {wq, wk, wv, wo};
    for (int g = 0; g < 4; g++)
        wt_split<<<dim3(32, 32), dim3(32, 8)>>>(ws[g], wthi + (size_t)g * DIM * DIM,
                                                wtlo + (size_t)g * DIM * DIM);

    const int SPLIT_BLKS = M_ROWS * DIM / 4 / 256;   // 8192
    dim3 gg(DIM / 128, M_ROWS / 128);                // (8, 64)

    split_a<<<SPLIT_BLKS, 256>>>((const float4*)q, (uint2*)ahi, (uint2*)alo);
    gemm_mma<<<gg, 256, GSMEM>>>(ahi, alo, wthi + 0 * (size_t)DIM * DIM, wtlo + 0 * (size_t)DIM * DIM, xq);

    split_a<<<SPLIT_BLKS, 256>>>((const float4*)k, (uint2*)ahi, (uint2*)alo);
    gemm_mma<<<gg, 256, GSMEM>>>(ahi, alo, wthi + 1 * (size_t)DIM * DIM, wtlo + 1 * (size_t)DIM * DIM, xk);

    split_a<<<SPLIT_BLKS, 256>>>((const float4*)v, (uint2*)ahi, (uint2*)alo);
    gemm_mma<<<gg, 256, GSMEM>>>(ahi, alo, wthi + 2 * (size_t)DIM * DIM, wtlo + 2 * (size_t)DIM * DIM, xv);

    dim3 ga(SEQ / QT, BATCH * NHEADS);  // (32, 64)
    attn_kernel<<<ga, 256, ATTN_SMEM>>>(xq, xk, xv, ao);

    split_a<<<SPLIT_BLKS, 256>>>((const float4*)ao, (uint2*)ahi, (uint2*)alo);
    gemm_mma<<<gg, 256, GSMEM>>>(ahi, alo, wthi + 3 * (size_t)DIM * DIM, wtlo + 3 * (size_t)DIM * DIM, out);
}

// round 13
// speedup vs baseline: 2.8277x; 1.7993x over previous
#include <cuda_runtime.h>
#include <cuda_bf16.h>
#include <cstdint>

#define DIM 1024
#define NHEADS 16
#define HD 64
#define BATCH 4
#define SEQ 2048
#define M_ROWS (BATCH * SEQ)   // 8192

// ---------------- scratch (no allocs allowed) ----------------
__device__ float g_xq[M_ROWS * DIM];
__device__ float g_xk[M_ROWS * DIM];
__device__ float g_xv[M_ROWS * DIM];
__device__ float g_ao[M_ROWS * DIM];
__device__ __nv_bfloat16 g_ahi[M_ROWS * DIM];
__device__ __nv_bfloat16 g_alo[M_ROWS * DIM];
__device__ __nv_bfloat16 g_wthi[4 * DIM * DIM];   // W^T hi, [n][k]
__device__ __nv_bfloat16 g_wtlo[4 * DIM * DIM];   // W^T lo

// ================= helpers =================
__device__ __forceinline__ uint32_t smem_to_u32(const void* p) {
    uint32_t a;
    asm("{ .reg .u64 t; cvta.to.shared.u64 t, %1; cvt.u32.u64 %0, t; }"
        : "=r"(a) : "l"(p));
    return a;
}

#define CP_ASYNC16(saddr, gptr) \
    asm volatile("cp.async.cg.shared.global [%0], [%1], 16;" \
                 :: "r"(saddr), "l"(gptr) : "memory")
#define CP_COMMIT() asm volatile("cp.async.commit_group;" ::: "memory")
#define CP_WAIT1() asm volatile("cp.async.wait_group 1;" ::: "memory")
#define CP_WAIT0() asm volatile("cp.async.wait_group 0;" ::: "memory")

#define MMA16816(c, a, b) \
    asm volatile("mma.sync.aligned.m16n8k16.row.col.f32.bf16.bf16.f32 " \
        "{%0,%1,%2,%3}, {%4,%5,%6,%7}, {%8,%9}, {%0,%1,%2,%3};" \
        : "+f"((c)[0]), "+f"((c)[1]), "+f"((c)[2]), "+f"((c)[3]) \
        : "r"((a)[0]), "r"((a)[1]), "r"((a)[2]), "r"((a)[3]), \
          "r"((b)[0]), "r"((b)[1]))

// split two floats into packed bf16x2 hi and lo residual
__device__ __forceinline__ void bfsplit2(float a, float b, uint32_t& hi, uint32_t& lo) {
    __nv_bfloat162 h, l;
    h.x = __float2bfloat16(a); h.y = __float2bfloat16(b);
    l.x = __float2bfloat16(a - __bfloat162float(h.x));
    l.y = __float2bfloat16(b - __bfloat162float(h.y));
    hi = *reinterpret_cast<uint32_t*>(&h);
    lo = *reinterpret_cast<uint32_t*>(&l);
}

// ================= prep kernels =================
__global__ __launch_bounds__(256) void split_a(const float4* __restrict__ in,
                                               uint2* __restrict__ oh,
                                               uint2* __restrict__ ol) {
    int idx = blockIdx.x * 256 + threadIdx.x;
    float4 v = in[idx];
    uint2 rh, rl;
    bfsplit2(v.x, v.y, rh.x, rl.x);
    bfsplit2(v.z, v.w, rh.y, rl.y);
    oh[idx] = rh; ol[idx] = rl;
}

__global__ void wt_split(const float* __restrict__ W,
                         __nv_bfloat16* __restrict__ Th,
                         __nv_bfloat16* __restrict__ Tl) {
    __shared__ float t[32][33];
    int n0 = blockIdx.x * 32, k0 = blockIdx.y * 32;
    int tx = threadIdx.x, ty = threadIdx.y;
#pragma unroll
    for (int i = ty; i < 32; i += 8)
        t[i][tx] = W[(size_t)(k0 + i) * DIM + n0 + tx];
    __syncthreads();
#pragma unroll
    for (int i = ty; i < 32; i += 8) {
        float x = t[tx][i];
        __nv_bfloat16 h = __float2bfloat16(x);
        __nv_bfloat16 l = __float2bfloat16(x - __bfloat162float(h));
        size_t o = (size_t)(n0 + i) * DIM + k0 + tx;
        Th[o] = h; Tl[o] = l;
    }
}

// ================= bf16x3 mma.sync GEMM (verified R6) =================
#define AROWB 144
#define TILEB (128 * AROWB)
#define BUFB (4 * TILEB)
#define GSMEM (2 * BUFB)

__global__ __launch_bounds__(256, 1) void gemm_mma(
    const __nv_bfloat16* __restrict__ Ahi, const __nv_bfloat16* __restrict__ Alo,
    const __nv_bfloat16* __restrict__ Bhi, const __nv_bfloat16* __restrict__ Blo,
    float* __restrict__ C)
{
    extern __shared__ char sm[];
    const uint32_t sb = smem_to_u32(sm);
    const int tid = threadIdx.x;
    const int wid = tid >> 5, lane = tid & 31;
    const int wm = wid >> 2, wn = wid & 3;
    const int g = lane >> 2, t = lane & 3;
    const int m0 = blockIdx.y * 128, n0 = blockIdx.x * 128;

    float acc[4][4][4];
#pragma unroll
    for (int mi = 0; mi < 4; mi++)
#pragma unroll
        for (int ni = 0; ni < 4; ni++)
#pragma unroll
            for (int j = 0; j < 4; j++) acc[mi][ni][j] = 0.f;

    uint32_t soff[4]; int arow[4], aseg[4];
#pragma unroll
    for (int u = 0; u < 4; u++) {
        int flat = u * 256 + tid;
        arow[u] = flat >> 3;
        aseg[u] = flat & 7;
        soff[u] = (uint32_t)(arow[u] * AROWB + aseg[u] * 16);
    }

    auto issue_chunk = [&](int c, int buf) {
        const int k0 = c * 64;
        const uint32_t bb = sb + buf * BUFB;
#pragma unroll
        for (int u = 0; u < 4; u++) {
            const size_t ga = (size_t)(m0 + arow[u]) * DIM + k0 + aseg[u] * 8;
            const size_t gb = (size_t)(n0 + arow[u]) * DIM + k0 + aseg[u] * 8;
            CP_ASYNC16(bb + 0 * TILEB + soff[u], Ahi + ga);
            CP_ASYNC16(bb + 1 * TILEB + soff[u], Alo + ga);
            CP_ASYNC16(bb + 2 * TILEB + soff[u], Bhi + gb);
            CP_ASYNC16(bb + 3 * TILEB + soff[u], Blo + gb);
        }
    };

    issue_chunk(0, 0);
    CP_COMMIT();

    for (int c = 0; c < DIM / 64; c++) {
        if (c < DIM / 64 - 1) {
            issue_chunk(c + 1, (c + 1) & 1);
            CP_COMMIT();
            CP_WAIT1();
        } else {
            CP_WAIT0();
        }
        __syncthreads();

        const char* bbp = sm + (c & 1) * BUFB;
#pragma unroll
        for (int ks = 0; ks < 4; ks++) {
            const int kb = ks * 32 + t * 4;
            uint32_t bh[4][2], bl[4][2];
#pragma unroll
            for (int ni = 0; ni < 4; ni++) {
                const uint32_t noff = (uint32_t)((wn * 32 + ni * 8 + g) * AROWB);
                bh[ni][0] = *(const uint32_t*)(bbp + 2 * TILEB + noff + kb);
                bh[ni][1] = *(const uint32_t*)(bbp + 2 * TILEB + noff + kb + 16);
                bl[ni][0] = *(const uint32_t*)(bbp + 3 * TILEB + noff + kb);
                bl[ni][1] = *(const uint32_t*)(bbp + 3 * TILEB + noff + kb + 16);
            }
#pragma unroll
            for (int mi = 0; mi < 4; mi++) {
                const uint32_t r0off = (uint32_t)((wm * 64 + mi * 16 + g) * AROWB);
                const uint32_t r1off = r0off + 8 * AROWB;
                uint32_t ah[4], al[4];
                ah[0] = *(const uint32_t*)(bbp + r0off + kb);
                ah[1] = *(const uint32_t*)(bbp + r1off + kb);
                ah[2] = *(const uint32_t*)(bbp + r0off + kb + 16);
                ah[3] = *(const uint32_t*)(bbp + r1off + kb + 16);
                al[0] = *(const uint32_t*)(bbp + TILEB + r0off + kb);
                al[1] = *(const uint32_t*)(bbp + TILEB + r1off + kb);
                al[2] = *(const uint32_t*)(bbp + TILEB + r0off + kb + 16);
                al[3] = *(const uint32_t*)(bbp + TILEB + r1off + kb + 16);
#pragma unroll
                for (int ni = 0; ni < 4; ni++) {
                    MMA16816(acc[mi][ni], ah, bh[ni]);
                    MMA16816(acc[mi][ni], ah, bl[ni]);
                    MMA16816(acc[mi][ni], al, bh[ni]);
                }
            }
        }
        __syncthreads();
    }

#pragma unroll
    for (int mi = 0; mi < 4; mi++) {
        const int r = m0 + wm * 64 + mi * 16 + g;
#pragma unroll
        for (int ni = 0; ni < 4; ni++) {
            const int cc = n0 + wn * 32 + ni * 8 + 2 * t;
            *reinterpret_cast<float2*>(C + (size_t)r * DIM + cc) =
                make_float2(acc[mi][ni][0], acc[mi][ni][1]);
            *reinterpret_cast<float2*>(C + (size_t)(r + 8) * DIM + cc) =
                make_float2(acc[mi][ni][2], acc[mi][ni][3]);
        }
    }
}

// ================= mma.sync flash attention (bf16x3) =================
// 64x64 Q/K tiles, 4 warps, each warp owns 16 query rows.
// smem rows: 64 bf16 elems = 128B, padded to 144B.
#define ATRB 144
#define ATTILE (64 * ATRB)            // 9216
#define AT_KH 0
#define AT_KL ATTILE
#define AT_VH (2 * ATTILE)
#define AT_VL (3 * ATTILE)
#define AT_QH (4 * ATTILE)
#define AT_QL (5 * ATTILE)
#define AT_VS (6 * ATTILE)            // 55296: fp32 V stage, 64 rows x 68 floats
#define ATTN2_SMEM (AT_VS + 64 * 68 * 4)   // 72704

__global__ __launch_bounds__(128, 1) void attn_mma(
    const float* __restrict__ XQ, const float* __restrict__ XK,
    const float* __restrict__ XV, float* __restrict__ O)
{
    extern __shared__ char sm[];
    float* vstage = reinterpret_cast<float*>(sm + AT_VS);

    const int tid = threadIdx.x;
    const int warp = tid >> 5, lane = tid & 31;
    const int g = lane >> 2, t = lane & 3;
    const int bh = blockIdx.y;
    const int b = bh >> 4, h = bh & 15;
    const int q0 = blockIdx.x * 64;
    const int rw = warp * 16;

    // ---- load Q tile (scaled by 1/sqrt(64)), split hi/lo ----
#pragma unroll
    for (int u = 0; u < 8; u++) {
        int f = u * 128 + tid;          // 1024 float4 slots
        int row = f >> 4, seg = f & 15;
        float4 v = *reinterpret_cast<const float4*>(
            XQ + (size_t)(b * SEQ + q0 + row) * DIM + h * HD + seg * 4);
        uint32_t h01, l01, h23, l23;
        bfsplit2(v.x * 0.125f, v.y * 0.125f, h01, l01);
        bfsplit2(v.z * 0.125f, v.w * 0.125f, h23, l23);
        *reinterpret_cast<uint2*>(sm + AT_QH + row * ATRB + seg * 8) = make_uint2(h01, h23);
        *reinterpret_cast<uint2*>(sm + AT_QL + row * ATRB + seg * 8) = make_uint2(l01, l23);
    }

    float m0v = -1e30f, m1v = -1e30f, l0v = 0.f, l1v = 0.f;
    float acc_o[8][4];
#pragma unroll
    for (int jd = 0; jd < 8; jd++)
#pragma unroll
        for (int r = 0; r < 4; r++) acc_o[jd][r] = 0.f;

    for (int jt = 0; jt <= (int)blockIdx.x; jt++) {
        const int k0g = jt * 64;
        __syncthreads();   // prev iteration readers done (also covers Q writes, iter 0)

        // ---- load K tile (split) + stage V tile fp32 ----
#pragma unroll
        for (int u = 0; u < 8; u++) {
            int f = u * 128 + tid;
            int row = f >> 4, seg = f & 15;
            const size_t gro = (size_t)(b * SEQ + k0g + row) * DIM + h * HD + seg * 4;
            float4 kv = *reinterpret_cast<const float4*>(XK + gro);
            uint32_t h01, l01, h23, l23;
            bfsplit2(kv.x, kv.y, h01, l01);
            bfsplit2(kv.z, kv.w, h23, l23);
            *reinterpret_cast<uint2*>(sm + AT_KH + row * ATRB + seg * 8) = make_uint2(h01, h23);
            *reinterpret_cast<uint2*>(sm + AT_KL + row * ATRB + seg * 8) = make_uint2(l01, l23);
            float4 vv = *reinterpret_cast<const float4*>(XV + gro);
            *reinterpret_cast<float4*>(vstage + row * 68 + seg * 4) = vv;
        }
        __syncthreads();

        // ---- transpose V: Vt[d][s] bf16 hi/lo ----
        {
            const int d = tid >> 1;
            const int s0 = (tid & 1) * 32;
#pragma unroll
            for (int j = 0; j < 16; j++) {
                int s = s0 + 2 * j;
                float a = vstage[(size_t)s * 68 + d];
                float c = vstage[(size_t)(s + 1) * 68 + d];
                uint32_t hi, lo;
                bfsplit2(a, c, hi, lo);
                *reinterpret_cast<uint32_t*>(sm + AT_VH + d * ATRB + s * 2) = hi;
                *reinterpret_cast<uint32_t*>(sm + AT_VL + d * ATRB + s * 2) = lo;
            }
        }
        __syncthreads();

        // ---- S = Q K^T (bf16x3) ----
        float s_[8][4];
#pragma unroll
        for (int j = 0; j < 8; j++)
#pragma unroll
            for (int r = 0; r < 4; r++) s_[j][r] = 0.f;

#pragma unroll
        for (int kk = 0; kk < 4; kk++) {
            const int kb = kk * 32 + t * 4;
            const char* qh = sm + AT_QH + (rw + g) * ATRB + kb;
            const char* ql = sm + AT_QL + (rw + g) * ATRB + kb;
            uint32_t ah[4], al[4];
            ah[0] = *(const uint32_t*)(qh);
            ah[1] = *(const uint32_t*)(qh + 8 * ATRB);
            ah[2] = *(const uint32_t*)(qh + 16);
            ah[3] = *(const uint32_t*)(qh + 8 * ATRB + 16);
            al[0] = *(const uint32_t*)(ql);
            al[1] = *(const uint32_t*)(ql + 8 * ATRB);
            al[2] = *(const uint32_t*)(ql + 16);
            al[3] = *(const uint32_t*)(ql + 8 * ATRB + 16);
#pragma unroll
            for (int j = 0; j < 8; j++) {
                const uint32_t nb = (uint32_t)((j * 8 + g) * ATRB + kb);
                uint32_t bhv[2], blv[2];
                bhv[0] = *(const uint32_t*)(sm + AT_KH + nb);
                bhv[1] = *(const uint32_t*)(sm + AT_KH + nb + 16);
                blv[0] = *(const uint32_t*)(sm + AT_KL + nb);
                blv[1] = *(const uint32_t*)(sm + AT_KL + nb + 16);
                MMA16816(s_[j], ah, bhv);
                MMA16816(s_[j], ah, blv);
                MMA16816(s_[j], al, bhv);
            }
        }

        // ---- causal mask (diagonal tile only) ----
        if (jt == (int)blockIdx.x) {
            const int rowA = q0 + rw + g;
            const int rowB = rowA + 8;
#pragma unroll
            for (int j = 0; j < 8; j++) {
                const int cb = k0g + j * 8 + 2 * t;
                if (cb > rowA)     s_[j][0] = -1e30f;
                if (cb + 1 > rowA) s_[j][1] = -1e30f;
                if (cb > rowB)     s_[j][2] = -1e30f;
                if (cb + 1 > rowB) s_[j][3] = -1e30f;
            }
        }

        // ---- online softmax (rows g and g+8; reduce over 4-lane t-group) ----
        float rmA = -1e30f, rmB = -1e30f;
#pragma unroll
        for (int j = 0; j < 8; j++) {
            rmA = fmaxf(rmA, fmaxf(s_[j][0], s_[j][1]));
            rmB = fmaxf(rmB, fmaxf(s_[j][2], s_[j][3]));
        }
        rmA = fmaxf(rmA, __shfl_xor_sync(0xffffffffu, rmA, 1));
        rmA = fmaxf(rmA, __shfl_xor_sync(0xffffffffu, rmA, 2));
        rmB = fmaxf(rmB, __shfl_xor_sync(0xffffffffu, rmB, 1));
        rmB = fmaxf(rmB, __shfl_xor_sync(0xffffffffu, rmB, 2));

        const float mA = fmaxf(m0v, rmA), mB = fmaxf(m1v, rmB);
        const float alphaA = __expf(m0v - mA), alphaB = __expf(m1v - mB);
        float rsA = 0.f, rsB = 0.f;
#pragma unroll
        for (int j = 0; j < 8; j++) {
            s_[j][0] = __expf(s_[j][0] - mA); rsA += s_[j][0];
            s_[j][1] = __expf(s_[j][1] - mA); rsA += s_[j][1];
            s_[j][2] = __expf(s_[j][2] - mB); rsB += s_[j][2];
            s_[j][3] = __expf(s_[j][3] - mB); rsB += s_[j][3];
        }
        rsA += __shfl_xor_sync(0xffffffffu, rsA, 1);
        rsA += __shfl_xor_sync(0xffffffffu, rsA, 2);
        rsB += __shfl_xor_sync(0xffffffffu, rsB, 1);
        rsB += __shfl_xor_sync(0xffffffffu, rsB, 2);
        l0v = l0v * alphaA + rsA; m0v = mA;
        l1v = l1v * alphaB + rsB; m1v = mB;
#pragma unroll
        for (int jd = 0; jd < 8; jd++) {
            acc_o[jd][0] *= alphaA; acc_o[jd][1] *= alphaA;
            acc_o[jd][2] *= alphaB; acc_o[jd][3] *= alphaB;
        }

        // ---- O += P V (bf16x3; P from registers) ----
#pragma unroll
        for (int kk = 0; kk < 4; kk++) {
            uint32_t pah[4], pal[4];
            bfsplit2(s_[2 * kk][0],     s_[2 * kk][1],     pah[0], pal[0]);
            bfsplit2(s_[2 * kk][2],     s_[2 * kk][3],     pah[1], pal[1]);
            bfsplit2(s_[2 * kk + 1][0], s_[2 * kk + 1][1], pah[2], pal[2]);
            bfsplit2(s_[2 * kk + 1][2], s_[2 * kk + 1][3], pah[3], pal[3]);
            const int kb = kk * 32 + t * 4;
#pragma unroll
            for (int jd = 0; jd < 8; jd++) {
                const uint32_t vb = (uint32_t)((jd * 8 + g) * ATRB + kb);
                uint32_t vh[2], vl[2];
                vh[0] = *(const uint32_t*)(sm + AT_VH + vb);
                vh[1] = *(const uint32_t*)(sm + AT_VH + vb + 16);
                vl[0] = *(const uint32_t*)(sm + AT_VL + vb);
                vl[1] = *(const uint32_t*)(sm + AT_VL + vb + 16);
                MMA16816(acc_o[jd], pah, vh);
                MMA16816(acc_o[jd], pah, vl);
                MMA16816(acc_o[jd], pal, vh);
            }
        }
    }

    // ---- normalize + write ----
    const float invA = 1.0f / l0v, invB = 1.0f / l1v;
    const size_t rowA = (size_t)(b * SEQ + q0 + rw + g);
#pragma unroll
    for (int jd = 0; jd < 8; jd++) {
        const int col = h * HD + jd * 8 + 2 * t;
        *reinterpret_cast<float2*>(O + rowA * DIM + col) =
            make_float2(acc_o[jd][0] * invA, acc_o[jd][1] * invA);
        *reinterpret_cast<float2*>(O + (rowA + 8) * DIM + col) =
            make_float2(acc_o[jd][2] * invB, acc_o[jd][3] * invB);
    }
}

// ---------------- launch ----------------
extern "C" void kernel_launch(void* const* d_in, const int* in_sizes, int n_in,
                              void* d_out, int out_size)
{
    const float* q  = (const float*)d_in[0];
    const float* k  = (const float*)d_in[1];
    const float* v  = (const float*)d_in[2];
    const float* wq = (const float*)d_in[3];
    const float* wk = (const float*)d_in[4];
    const float* wv = (const float*)d_in[5];
    const float* wo = (const float*)d_in[6];
    float* out = (float*)d_out;

    float *xq, *xk, *xv, *ao;
    __nv_bfloat16 *ahi, *alo, *wthi, *wtlo;
    cudaGetSymbolAddress((void**)&xq, g_xq);
    cudaGetSymbolAddress((void**)&xk, g_xk);
    cudaGetSymbolAddress((void**)&xv, g_xv);
    cudaGetSymbolAddress((void**)&ao, g_ao);
    cudaGetSymbolAddress((void**)&ahi, g_ahi);
    cudaGetSymbolAddress((void**)&alo, g_alo);
    cudaGetSymbolAddress((void**)&wthi, g_wthi);
    cudaGetSymbolAddress((void**)&wtlo, g_wtlo);

    cudaFuncSetAttribute(gemm_mma, cudaFuncAttributeMaxDynamicSharedMemorySize, GSMEM);
    cudaFuncSetAttribute(attn_mma, cudaFuncAttributeMaxDynamicSharedMemorySize, ATTN2_SMEM);

    const float* ws[4] = {wq, wk, wv, wo};
    for (int g2 = 0; g2 < 4; g2++)
        wt_split<<<dim3(32, 32), dim3(32, 8)>>>(ws[g2], wthi + (size_t)g2 * DIM * DIM,
                                                wtlo + (size_t)g2 * DIM * DIM);

    const int SPLIT_BLKS = M_ROWS * DIM / 4 / 256;
    dim3 gg(DIM / 128, M_ROWS / 128);

    split_a<<<SPLIT_BLKS, 256>>>((const float4*)q, (uint2*)ahi, (uint2*)alo);
    gemm_mma<<<gg, 256, GSMEM>>>(ahi, alo, wthi + 0 * (size_t)DIM * DIM, wtlo + 0 * (size_t)DIM * DIM, xq);

    split_a<<<SPLIT_BLKS, 256>>>((const float4*)k, (uint2*)ahi, (uint2*)alo);
    gemm_mma<<<gg, 256, GSMEM>>>(ahi, alo, wthi + 1 * (size_t)DIM * DIM, wtlo + 1 * (size_t)DIM * DIM, xk);

    split_a<<<SPLIT_BLKS, 256>>>((const float4*)v, (uint2*)ahi, (uint2*)alo);
    gemm_mma<<<gg, 256, GSMEM>>>(ahi, alo, wthi + 2 * (size_t)DIM * DIM, wtlo + 2 * (size_t)DIM * DIM, xv);

    dim3 ga(SEQ / 64, BATCH * NHEADS);   // (32, 64)
    attn_mma<<<ga, 128, ATTN2_SMEM>>>(xq, xk, xv, ao);

    split_a<<<SPLIT_BLKS, 256>>>((const float4*)ao, (uint2*)ahi, (uint2*)alo);
    gemm_mma<<<gg, 256, GSMEM>>>(ahi, alo, wthi + 3 * (size_t)DIM * DIM, wtlo + 3 * (size_t)DIM * DIM, out);
}